// round 8
// baseline (speedup 1.0000x reference)
#include <cuda_runtime.h>
#include <cuda_bf16.h>

// BumpX: out[b,l,f] = sum_g mask(g-f, aa[b,l,f]) * x[b,l,g] / sum_g mask(...)
// mask(d,a) = 1 - gg(arg), arg = (d^2 - a^2)/(6a+9), gg(t)=ff(t)/(ff(t)+ff(1-t)),
// ff(t)=exp(-1/clamp(softplus(t),1e-6)).
//
// Round 8: latency attack. d takes only 8 values and a in [0,1), so bake
// EIGHT per-d tables mask_d(a) (256 lerp segments in a, compile-time
// constexpr double precision, exact reference formula incl. clamps).
// A thread's 4 masks (its tap-parity half) share ONE index i=floor(a*256)
// and fraction -> stored as {float4 node, float4 delta} per (parity, i):
// the 4 divergent LUT gathers collapse to 2 contiguous LDG.128, and the
// dependency chain loses rcp(6a+9), a^2 and all per-tap arg FMAs.
// d=0's 0.5 weight (double-count fix) is baked into the table.
// Lerp-in-a error <= ~3e-5 abs vs the 1e-3 rel gate. Taps |d|>=8 have
// mask <= 4e-11 -> window is numerically identical to dense fp32.
//
// Structure: 2 threads/output (h=0: d=0,2,4,6; h=1: d=1,3,5,7), shfl_xor
// combine, no smem/syncthreads, interior blocks drop boundary predicates.

#define BX_F    1024
#define BX_OPB  128
#define BX_TPB  256
#define BX_AN   256          // lerp segments in a

// ---------- compile-time math (double precision) ----------
constexpr double BX_LN2 = 0.6931471805599453;

constexpr double bx_cexp(double x) {            // |x| <= ~1e6/clamped use
    int n = (int)(x / BX_LN2 + (x >= 0.0 ? 0.5 : -0.5));
    double r = x - n * BX_LN2;
    double s = 1.0, term = 1.0;
    for (int k = 1; k <= 12; ++k) { term *= r / k; s += term; }
    double p = 1.0;
    int m = n < 0 ? -n : n;
    if (m > 1100) return n < 0 ? 0.0 : 1e308;   // hard under/overflow guard
    for (int i = 0; i < m; ++i) p *= 2.0;
    return n < 0 ? s / p : s * p;
}
constexpr double bx_clog1p(double z) {          // z in (0, 1]
    double w = z / (z + 2.0);
    double w2 = w * w, s = 0.0, t = w;
    for (int k = 1; k <= 15; k += 2) { s += t / k; t *= w2; }
    return 2.0 * s;
}
constexpr double bx_csoftplus(double t) {
    double z = bx_cexp(t < 0.0 ? t : -t);
    double l = bx_clog1p(z);
    return (t > 0.0 ? t : 0.0) + l;
}
constexpr double bx_cmask_arg(double arg) {     // 1 - gg(arg), exact formula
    double u = bx_csoftplus(arg);        if (u < 1e-6) u = 1e-6;
    double v = bx_csoftplus(1.0 - arg);  if (v < 1e-6) v = 1e-6;
    double f1 = bx_cexp(-1.0 / u);
    double f2 = bx_cexp(-1.0 / v);
    if (f1 + f2 == 0.0) return 0.0;             // both underflow: mask -> 0
    return f2 / (f1 + f2);
}
constexpr double bx_cmask_da(int d, double a) {
    double arg = ((double)(d * d) - a * a) / (6.0 * a + 9.0);
    return bx_cmask_arg(arg);
}

struct BxEnt { float4 m; float4 dm; };          // node values + deltas (lerp)
struct BxTab { BxEnt e[2][BX_AN]; };            // [parity][i] : 16 KB

constexpr BxTab bx_make_tab() {
    BxTab T{};
    for (int h = 0; h < 2; ++h) {
        for (int i = 0; i < BX_AN; ++i) {
            double a0 = (double)i       / BX_AN;
            double a1 = (double)(i + 1) / BX_AN;
            double v0[4] = {}, v1[4] = {};
            for (int k = 0; k < 4; ++k) {
                int d = 2 * k + h;
                double w = (d == 0) ? 0.5 : 1.0;    // bake d=0 double-count fix
                v0[k] = w * bx_cmask_da(d, a0);
                v1[k] = w * bx_cmask_da(d, a1);
            }
            T.e[h][i].m.x  = (float)v0[0];
            T.e[h][i].m.y  = (float)v0[1];
            T.e[h][i].m.z  = (float)v0[2];
            T.e[h][i].m.w  = (float)v0[3];
            T.e[h][i].dm.x = (float)(v1[0] - v0[0]);
            T.e[h][i].dm.y = (float)(v1[1] - v0[1]);
            T.e[h][i].dm.z = (float)(v1[2] - v0[2]);
            T.e[h][i].dm.w = (float)(v1[3] - v0[3]);
        }
    }
    return T;
}

__device__ const BxTab bx_tab = bx_make_tab();

// ---------- runtime ----------
__device__ __forceinline__ float bx_rcp(float x) {
    float r; asm("rcp.approx.ftz.f32 %0, %1;" : "=f"(r) : "f"(x)); return r;
}

template <bool INTERIOR>
__device__ __forceinline__ void bx_body(const float* __restrict__ x,
                                        const float* __restrict__ aa,
                                        float* __restrict__ out,
                                        int row, int fbase)
{
    const int o = (int)threadIdx.x >> 1;   // output within block
    const int h = (int)threadIdx.x & 1;    // tap-parity half

    const int f = fbase + o;
    const float* xr = x + row * BX_F;

    const float a  = __ldg(aa + row * BX_F + f);

    // shared lerp index/fraction for all 4 masks of this half
    float t  = a * (float)BX_AN;
    int   i  = min((int)t, BX_AN - 1);
    float fr = t - (float)i;

    const BxEnt* e = &bx_tab.e[h][i];
    float4 m4 = __ldg(&e->m);
    float4 d4 = __ldg(&e->dm);

    float mk[4];
    mk[0] = fmaf(fr, d4.x, m4.x);
    mk[1] = fmaf(fr, d4.y, m4.y);
    mk[2] = fmaf(fr, d4.z, m4.z);
    mk[3] = fmaf(fr, d4.w, m4.w);

    float ws = 0.0f;
    float dn = 0.0f;

    // h==0: d = 0,2,4,6 ; h==1: d = 1,3,5,7
    #pragma unroll
    for (int k = 0; k < 4; ++k) {
        const int d = 2 * k + h;
        if (INTERIOR) {
            ws = fmaf(mk[k], __ldg(xr + f - d) + __ldg(xr + f + d), ws);
            dn += mk[k];
        } else {
            const bool  lo = (f >= d);
            const bool  hi = (f + d < BX_F);
            const float xl = lo ? __ldg(xr + f - d) : 0.0f;
            const float xh = hi ? __ldg(xr + f + d) : 0.0f;
            ws = fmaf(mk[k], xl + xh, ws);
            dn = fmaf(mk[k], (float)((int)lo + (int)hi), dn);
        }
    }

    float den = INTERIOR ? (dn + dn) : dn;

    ws  += __shfl_xor_sync(0xFFFFFFFFu, ws,  1);
    den += __shfl_xor_sync(0xFFFFFFFFu, den, 1);

    if (h == 0)
        out[row * BX_F + f] = ws * bx_rcp(den);
}

__global__ __launch_bounds__(BX_TPB)
void BumpX_kernel(const float* __restrict__ x,
                  const float* __restrict__ aa,
                  float* __restrict__ out)
{
    const int row   = blockIdx.x >> 3;              // b*L + l
    const int chunk = blockIdx.x & 7;
    const int fbase = chunk * BX_OPB;

    if (chunk != 0 && chunk != 7)
        bx_body<true>(x, aa, out, row, fbase);
    else
        bx_body<false>(x, aa, out, row, fbase);
}

extern "C" void kernel_launch(void* const* d_in, const int* in_sizes, int n_in,
                              void* d_out, int out_size)
{
    const float* x  = (const float*)d_in[0];
    const float* aa = (const float*)d_in[1];
    float* out      = (float*)d_out;

    const int rows = out_size / BX_F;               // B*L = 128
    dim3 grid(rows * (BX_F / BX_OPB));              // 1024 blocks
    BumpX_kernel<<<grid, BX_TPB>>>(x, aa, out);
}